// round 1
// baseline (speedup 1.0000x reference)
#include <cuda_runtime.h>

#define NCELLS   512
#define CDIM     64
#define CPAD     513          // 513 mod 32 == 1 -> conflict-free transpose STS and compute LDS
#define THREADS  256
#define TXN      64           // threads along cell dim
#define TYN      4            // thread groups along row dim
#define RPT      4            // rows per thread
#define CPT      8            // cells per thread (strided by 64 -> coalesced stores)
#define ROW_TILE (TYN * RPT)  // 16 rows per block
#define NWARPS   (THREADS / 32)

// Force an fma the frontend cannot pre-fold; immediates -2.0 / 0.5 keep ptxas
// from demoting to FADD, targeting the rt=1 FFMA-imm form.
__device__ __forceinline__ float ffma(float a, float b, float c) {
    float d;
    asm("fma.rn.f32 %0, %1, %2, %3;" : "=f"(d) : "f"(a), "f"(b), "f"(c));
    return d;
}

extern __shared__ float smem[];

__global__ __launch_bounds__(THREADS, 1)
void placecells_kernel(const float* __restrict__ x,
                       const float* __restrict__ cells,
                       float* __restrict__ out)
{
    float* cells_s = smem;                       // CDIM * CPAD
    float* xs_s    = cells_s + CDIM * CPAD;      // ROW_TILE * CDIM   (holds 2*x)
    float* redmax  = xs_s + ROW_TILE * CDIM;     // NWARPS * RPT
    float* redsum  = redmax + NWARPS * RPT;      // NWARPS * RPT

    const int tid  = threadIdx.x;
    const int tx   = tid & 63;
    const int ty   = tid >> 6;
    const int warp = tid >> 5;
    const int lane = tid & 31;
    const int rowbase = blockIdx.x * ROW_TILE;

    // ---- stage cells transposed (k-major) into smem ----
    // i consecutive per lane -> coalesced LDG; with CPAD=513 the STS banks are
    // (k + c) mod 32, k consecutive within a warp -> conflict-free.
    for (int i = tid; i < NCELLS * CDIM; i += THREADS) {
        int c = i >> 6, k = i & 63;
        cells_s[k * CPAD + c] = cells[i];
    }
    // ---- stage x, pre-scaled by 2 ----
    const float* xg = x + (size_t)rowbase * CDIM;
    for (int i = tid; i < ROW_TILE * CDIM; i += THREADS)
        xs_s[i] = 2.0f * xg[i];
    __syncthreads();

    float acc[RPT][CPT];
    #pragma unroll
    for (int r = 0; r < RPT; r++)
        #pragma unroll
        for (int j = 0; j < CPT; j++)
            acc[r][j] = 0.0f;

    const int myrow0 = ty * RPT;

    #pragma unroll
    for (int k0 = 0; k0 < CDIM; k0 += 4) {
        float4 xv[RPT];
        #pragma unroll
        for (int r = 0; r < RPT; r++)
            xv[r] = *reinterpret_cast<const float4*>(&xs_s[(myrow0 + r) * CDIM + k0]);

        #pragma unroll
        for (int kk = 0; kk < 4; kk++) {
            float cv[CPT];
            #pragma unroll
            for (int j = 0; j < CPT; j++)
                cv[j] = cells_s[(k0 + kk) * CPAD + tx + 64 * j];   // lanes consecutive -> no conflicts

            #pragma unroll
            for (int r = 0; r < RPT; r++) {
                float xk = (kk == 0) ? xv[r].x : (kk == 1) ? xv[r].y
                          : (kk == 2) ? xv[r].z : xv[r].w;         // xk = 2*x
                #pragma unroll
                for (int j = 0; j < CPT; j++) {
                    float t = ffma(cv[j], -2.0f, xk);              // 2*(x - c)
                    acc[r][j] = ffma(fabsf(t), 0.5f, acc[r][j]);   // += |x - c|
                }
            }
        }
    }

    // ---- softmax over 512 cells per row ----
    // unnormalized u = -0.5 * L1^2  (FIELD_SIZE = 1)
    float u[RPT][CPT];
    float m[RPT];
    #pragma unroll
    for (int r = 0; r < RPT; r++) {
        m[r] = -3.4e38f;
        #pragma unroll
        for (int j = 0; j < CPT; j++) {
            float a = acc[r][j];
            float v = -0.5f * a * a;
            u[r][j] = v;
            m[r] = fmaxf(m[r], v);
        }
    }
    // warp reduce max (all 32 lanes share the same rows: same ty)
    #pragma unroll
    for (int off = 16; off > 0; off >>= 1)
        #pragma unroll
        for (int r = 0; r < RPT; r++)
            m[r] = fmaxf(m[r], __shfl_xor_sync(0xffffffffu, m[r], off));
    if (lane == 0)
        #pragma unroll
        for (int r = 0; r < RPT; r++)
            redmax[warp * RPT + r] = m[r];
    __syncthreads();

    float s[RPT];
    #pragma unroll
    for (int r = 0; r < RPT; r++) {
        float rm = fmaxf(redmax[(2 * ty) * RPT + r], redmax[(2 * ty + 1) * RPT + r]);
        s[r] = 0.0f;
        #pragma unroll
        for (int j = 0; j < CPT; j++) {
            float e = exp2f((u[r][j] - rm) * 1.4426950408889634f);
            u[r][j] = e;
            s[r] += e;
        }
    }
    #pragma unroll
    for (int off = 16; off > 0; off >>= 1)
        #pragma unroll
        for (int r = 0; r < RPT; r++)
            s[r] += __shfl_xor_sync(0xffffffffu, s[r], off);
    if (lane == 0)
        #pragma unroll
        for (int r = 0; r < RPT; r++)
            redsum[warp * RPT + r] = s[r];
    __syncthreads();

    #pragma unroll
    for (int r = 0; r < RPT; r++) {
        float rs  = redsum[(2 * ty) * RPT + r] + redsum[(2 * ty + 1) * RPT + r];
        float inv = 1.0f / rs;
        const int row = rowbase + myrow0 + r;
        float* orow = out + (size_t)row * NCELLS;
        #pragma unroll
        for (int j = 0; j < CPT; j++)
            orow[tx + 64 * j] = u[r][j] * inv;   // lanes consecutive -> coalesced
    }
}

extern "C" void kernel_launch(void* const* d_in, const int* in_sizes, int n_in,
                              void* d_out, int out_size)
{
    const float* x     = (const float*)d_in[0];   // 8192 x 64
    const float* cells = (const float*)d_in[1];   // 512 x 64
    float* out = (float*)d_out;                   // 8192 x 512

    int nrows = in_sizes[0] / CDIM;               // 8192
    int nblocks = nrows / ROW_TILE;               // 512

    size_t smem_bytes = (size_t)(CDIM * CPAD + ROW_TILE * CDIM + 2 * NWARPS * RPT) * sizeof(float);
    cudaFuncSetAttribute(placecells_kernel,
                         cudaFuncAttributeMaxDynamicSharedMemorySize, (int)smem_bytes);

    placecells_kernel<<<nblocks, THREADS, smem_bytes>>>(x, cells, out);
}

// round 4
// speedup vs baseline: 1.6031x; 1.6031x over previous
#include <cuda_runtime.h>

#define NCELLS   512
#define CDIM     64
#define CROW     68           // padded cell row (floats): 68 % 4 == 0 -> float4 aligned;
                              // word stride 17 -> conflict-free LDS.128 across lanes
#define THREADS  512
#define TYN      8            // row groups (tid >> 6)
#define RPT      4            // rows per thread
#define CPT      8            // cells per thread, strided by 64 (tx + 64*j)
#define ROW_TILE (TYN * RPT)  // 32 rows per block
#define NWARPS   (THREADS / 32)

// fma with immediate multiplier ptxas can't fold away (targets FFMA-imm rt=1).
__device__ __forceinline__ float ffma(float a, float b, float c) {
    float d;
    asm("fma.rn.f32 %0, %1, %2, %3;" : "=f"(d) : "f"(a), "f"(b), "f"(c));
    return d;
}

extern __shared__ float smem[];

__global__ __launch_bounds__(THREADS, 1)
void placecells_kernel(const float* __restrict__ x,
                       const float* __restrict__ cells,
                       float* __restrict__ out)
{
    float* cells_s = smem;                        // NCELLS * CROW (c-major, natural)
    float* xs_s    = cells_s + NCELLS * CROW;     // ROW_TILE * CDIM (holds 2*x)
    float* redmax  = xs_s + ROW_TILE * CDIM;      // NWARPS * RPT
    float* redsum  = redmax + NWARPS * RPT;       // NWARPS * RPT

    const int tid  = threadIdx.x;
    const int tx   = tid & 63;                    // cell lane: owns cells {tx + 64j}
    const int ty   = tid >> 6;                    // row group
    const int warp = tid >> 5;
    const int lane = tid & 31;
    const int rowbase = blockIdx.x * ROW_TILE;

    // ---- stage cells: straight float4 copy into padded rows (no transpose) ----
    {
        const float4* cg = reinterpret_cast<const float4*>(cells);
        for (int i = tid; i < NCELLS * (CDIM / 4); i += THREADS) {
            int c = i >> 4, w = i & 15;           // 16 float4 words per cell
            *reinterpret_cast<float4*>(&cells_s[c * CROW + w * 4]) = cg[i];
        }
    }
    // ---- stage x, pre-scaled by 2 ----
    {
        const float4* xg = reinterpret_cast<const float4*>(x + (size_t)rowbase * CDIM);
        for (int i = tid; i < ROW_TILE * (CDIM / 4); i += THREADS) {
            float4 v = xg[i];
            v.x *= 2.0f; v.y *= 2.0f; v.z *= 2.0f; v.w *= 2.0f;
            *reinterpret_cast<float4*>(&xs_s[i * 4]) = v;
        }
    }
    __syncthreads();

    float acc[RPT][CPT];
    #pragma unroll
    for (int r = 0; r < RPT; r++)
        #pragma unroll
        for (int j = 0; j < CPT; j++)
            acc[r][j] = 0.0f;

    const int myrow0 = ty * RPT;

    #pragma unroll 1
    for (int k0 = 0; k0 < CDIM; k0 += 4) {
        // 8x LDS.128: word index 17*tx + const -> distinct mod 8 per quarter-warp
        float4 cv[CPT];
        #pragma unroll
        for (int j = 0; j < CPT; j++)
            cv[j] = *reinterpret_cast<const float4*>(&cells_s[(tx + 64 * j) * CROW + k0]);

        // 4x broadcast LDS.128 (all lanes in a warp share ty -> same address)
        float4 xv[RPT];
        #pragma unroll
        for (int r = 0; r < RPT; r++)
            xv[r] = *reinterpret_cast<const float4*>(&xs_s[(myrow0 + r) * CDIM + k0]);

        #pragma unroll
        for (int kk = 0; kk < 4; kk++) {
            #pragma unroll
            for (int r = 0; r < RPT; r++) {
                float xk = (kk == 0) ? xv[r].x : (kk == 1) ? xv[r].y
                          : (kk == 2) ? xv[r].z : xv[r].w;          // xk = 2*x
                #pragma unroll
                for (int j = 0; j < CPT; j++) {
                    float ck = (kk == 0) ? cv[j].x : (kk == 1) ? cv[j].y
                              : (kk == 2) ? cv[j].z : cv[j].w;
                    float t = ffma(ck, -2.0f, xk);                  // 2*(x - c)
                    acc[r][j] = ffma(fabsf(t), 0.5f, acc[r][j]);    // += |x - c|
                }
            }
        }
    }

    // ---- softmax: u = -0.5 * L1^2 over 512 cells per row ----
    float m[RPT];
    #pragma unroll
    for (int r = 0; r < RPT; r++) {
        m[r] = -3.4e38f;
        #pragma unroll
        for (int j = 0; j < CPT; j++) {
            float a = acc[r][j];
            float v = -0.5f * a * a;
            acc[r][j] = v;                        // reuse acc as u
            m[r] = fmaxf(m[r], v);
        }
    }
    #pragma unroll
    for (int off = 16; off > 0; off >>= 1)
        #pragma unroll
        for (int r = 0; r < RPT; r++)
            m[r] = fmaxf(m[r], __shfl_xor_sync(0xffffffffu, m[r], off));
    if (lane == 0)
        #pragma unroll
        for (int r = 0; r < RPT; r++)
            redmax[warp * RPT + r] = m[r];
    __syncthreads();

    float s[RPT];
    #pragma unroll
    for (int r = 0; r < RPT; r++) {
        float rm = fmaxf(redmax[(2 * ty) * RPT + r], redmax[(2 * ty + 1) * RPT + r]);
        s[r] = 0.0f;
        #pragma unroll
        for (int j = 0; j < CPT; j++) {
            float e = exp2f((acc[r][j] - rm) * 1.4426950408889634f);
            acc[r][j] = e;
            s[r] += e;
        }
    }
    #pragma unroll
    for (int off = 16; off > 0; off >>= 1)
        #pragma unroll
        for (int r = 0; r < RPT; r++)
            s[r] += __shfl_xor_sync(0xffffffffu, s[r], off);
    if (lane == 0)
        #pragma unroll
        for (int r = 0; r < RPT; r++)
            redsum[warp * RPT + r] = s[r];
    __syncthreads();

    #pragma unroll
    for (int r = 0; r < RPT; r++) {
        float rs  = redsum[(2 * ty) * RPT + r] + redsum[(2 * ty + 1) * RPT + r];
        float inv = 1.0f / rs;
        const int row = rowbase + myrow0 + r;
        float* orow = out + (size_t)row * NCELLS;
        #pragma unroll
        for (int j = 0; j < CPT; j++)
            orow[tx + 64 * j] = acc[r][j] * inv;  // lanes consecutive -> coalesced STG.32
    }
}

extern "C" void kernel_launch(void* const* d_in, const int* in_sizes, int n_in,
                              void* d_out, int out_size)
{
    const float* x     = (const float*)d_in[0];   // 8192 x 64
    const float* cells = (const float*)d_in[1];   // 512 x 64
    float* out = (float*)d_out;                   // 8192 x 512

    int nrows = in_sizes[0] / CDIM;               // 8192
    int nblocks = nrows / ROW_TILE;               // 256

    size_t smem_bytes = (size_t)(NCELLS * CROW + ROW_TILE * CDIM + 2 * NWARPS * RPT) * sizeof(float);
    cudaFuncSetAttribute(placecells_kernel,
                         cudaFuncAttributeMaxDynamicSharedMemorySize, (int)smem_bytes);

    placecells_kernel<<<nblocks, THREADS, smem_bytes>>>(x, cells, out);
}